// round 1
// baseline (speedup 1.0000x reference)
#include <cuda_runtime.h>

// Batch-invariant trig of the trainable weights: cw[i]=cos(w_i/2), sw[i]=sin(w_i/2).
__device__ float g_wtrig[8];

__global__ void wtrig_kernel(const float* __restrict__ w) {
    int i = threadIdx.x;
    if (i < 4) {
        float h = 0.5f * w[i];
        // precise trig here (4 threads total, cost irrelevant; weights ~N(0,1))
        g_wtrig[i]     = cosf(h);
        g_wtrig[4 + i] = sinf(h);
    }
}

__global__ void __launch_bounds__(256)
qlayer_kernel(const float* __restrict__ x, float* __restrict__ out, int n) {
    int b = blockIdx.x * blockDim.x + threadIdx.x;
    if (b >= n) return;

    // x row is 8 floats; we need the first 4. 16B-aligned vector load.
    float4 xv = reinterpret_cast<const float4*>(x)[b * 2];

    float c0, s0, c1, s1, c2, s2, c3, s3;
    __sincosf(0.5f * xv.x, &s0, &c0);
    __sincosf(0.5f * xv.y, &s1, &c1);
    __sincosf(0.5f * xv.z, &s2, &c2);
    __sincosf(0.5f * xv.w, &s3, &c3);

    // Entangled state after CNOT chain (0->1,1->2,2->3) applied to the RY product
    // state: A[i0,i1,i2,i3] = f0[i0]*f1[i1^i0]*f2[i2^i1]*f3[i3^i2].
    float f0[2] = {c0, s0};
    float f1[2] = {c1, s1};
    float f2[2] = {c2, s2};
    float f3[2] = {c3, s3};

    float a[16];
#pragma unroll
    for (int i = 0; i < 16; i++) {
        int i0 = (i >> 3) & 1;
        int i1 = (i >> 2) & 1;
        int i2 = (i >> 1) & 1;
        int i3 = i & 1;
        a[i] = f0[i0] * f1[i1 ^ i0] * f2[i2 ^ i1] * f3[i3 ^ i2];
    }

    // Trainable RY layer on each wire. wire w acts on index bit (3-w).
    float cw[4], sw[4];
#pragma unroll
    for (int i = 0; i < 4; i++) {
        cw[i] = g_wtrig[i];
        sw[i] = g_wtrig[4 + i];
    }

#pragma unroll
    for (int w = 0; w < 4; w++) {
        int m = 8 >> w;
        float cc = cw[w], ss = sw[w];
#pragma unroll
        for (int i = 0; i < 16; i++) {
            if ((i & m) == 0) {
                float a0 = a[i], a1 = a[i | m];
                a[i]     = cc * a0 - ss * a1;
                a[i | m] = ss * a0 + cc * a1;
            }
        }
    }

    // <Z_w> = sum_i a[i]^2 * (bit_w(i) ? -1 : +1)
    float e0 = 0.f, e1 = 0.f, e2 = 0.f, e3 = 0.f;
#pragma unroll
    for (int i = 0; i < 16; i++) {
        float p = a[i] * a[i];
        e0 += (i & 8) ? -p : p;
        e1 += (i & 4) ? -p : p;
        e2 += (i & 2) ? -p : p;
        e3 += (i & 1) ? -p : p;
    }

    float4 o;
    o.x = e0; o.y = e1; o.z = e2; o.w = e3;
    reinterpret_cast<float4*>(out)[b] = o;
}

extern "C" void kernel_launch(void* const* d_in, const int* in_sizes, int n_in,
                              void* d_out, int out_size) {
    const float* x = (const float*)d_in[0];        // [B, 8]
    const float* weights = (const float*)d_in[1];  // [4]
    float* out = (float*)d_out;                    // [B, 4]
    int n = in_sizes[0] / 8;

    wtrig_kernel<<<1, 4>>>(weights);
    qlayer_kernel<<<(n + 255) / 256, 256>>>(x, out, n);
}

// round 3
// speedup vs baseline: 1.3446x; 1.3446x over previous
#include <cuda_runtime.h>

// Closed form of the whole circuit (XOR change of basis untangles the CNOT
// chain into a product state; double-angle identities collapse the Z/X
// expectations):
//   e_w = cos(theta_w) * prod_{k<=w} cos(x_k)  -  sin(theta_w) * sin(x_w) * sin(x_{w+1})
// with sin(x_4) := 1.
__global__ void __launch_bounds__(256)
qlayer_kernel(const float* __restrict__ x, const float* __restrict__ w,
              float* __restrict__ out, int n) {
    int t = blockIdx.x * blockDim.x + threadIdx.x;

    // weights: uniform across threads (L1/L2 broadcast); sincos once per thread,
    // amortized over 2 elements.
    float4 wv = *reinterpret_cast<const float4*>(w);
    float sw0, cw0, sw1, cw1, sw2, cw2, sw3, cw3;
    __sincosf(wv.x, &sw0, &cw0);
    __sincosf(wv.y, &sw1, &cw1);
    __sincosf(wv.z, &sw2, &cw2);
    __sincosf(wv.w, &sw3, &cw3);

#pragma unroll
    for (int e = 0; e < 2; e++) {
        int b = t * 2 + e;
        if (b >= n) break;

        // x row is 8 floats; we need the first 4 (16B-aligned vector load).
        float4 xv = reinterpret_cast<const float4*>(x)[b * 2];

        float s0, c0, s1, c1, s2, c2, s3, c3;
        __sincosf(xv.x, &s0, &c0);
        __sincosf(xv.y, &s1, &c1);
        __sincosf(xv.z, &s2, &c2);
        __sincosf(xv.w, &s3, &c3);

        // Z-parity chains
        float d0 = c0;
        float d1 = d0 * c1;
        float d2 = d1 * c2;
        float d3 = d2 * c3;
        // X correlators
        float X0 = s0 * s1;
        float X1 = s1 * s2;
        float X2 = s2 * s3;
        float X3 = s3;

        float4 o;
        o.x = fmaf(cw0, d0, -sw0 * X0);
        o.y = fmaf(cw1, d1, -sw1 * X1);
        o.z = fmaf(cw2, d2, -sw2 * X2);
        o.w = fmaf(cw3, d3, -sw3 * X3);
        reinterpret_cast<float4*>(out)[b] = o;
    }
}

extern "C" void kernel_launch(void* const* d_in, const int* in_sizes, int n_in,
                              void* d_out, int out_size) {
    const float* x = (const float*)d_in[0];        // [B, 8]
    const float* weights = (const float*)d_in[1];  // [4]
    float* out = (float*)d_out;                    // [B, 4]
    int n = in_sizes[0] / 8;

    int threads = 256;
    int elts_per_block = threads * 2;
    int blocks = (n + elts_per_block - 1) / elts_per_block;
    qlayer_kernel<<<blocks, threads>>>(x, weights, out, n);
}